// round 1
// baseline (speedup 1.0000x reference)
#include <cuda_runtime.h>

#define SS 512
#define NUNITS 9
#define DSTRIDE 520   // 512 + 8 zero pad, multiple of 4 -> float4-aligned rows
#define MAXB 128

// Scratch: zero-padded diagonal table diag[b][j], j in [0,520), pads = 0.
__device__ float g_diag[MAXB * DSTRIDE];

// Kernel A: gather the diagonal of each batch slice, write zeros into the pad.
__global__ void diag_kernel(const float* __restrict__ in, int B) {
    int idx = blockIdx.x * blockDim.x + threadIdx.x;
    int total = B * DSTRIDE;
    if (idx >= total) return;
    int b = idx / DSTRIDE;
    int j = idx - b * DSTRIDE;
    float v = 0.0f;
    if (j < SS) v = in[(size_t)b * SS * SS + (size_t)j * (SS + 1)];
    g_diag[idx] = v;
}

// Kernel B: each thread owns (i, j0..j0+3) and a slice of batches.
// Weights (pre-masked, pre-scaled by 9) + bias live in registers across the
// batch loop; per batch: 3x LDG.128 (diag window, L2-resident), 36 FMA,
// 1x STG.128.
__global__ __launch_bounds__(128)
void cnn_kernel(const float* __restrict__ w,
                const float* __restrict__ bb,
                float* __restrict__ out,
                int B, int bper) {
    int i  = blockIdx.x;          // 0..511
    int j0 = threadIdx.x << 2;    // 0,4,...,508
    int b0 = blockIdx.y * bper;
    int b1 = b0 + bper;
    if (b1 > B) b1 = B;

    float wv[36];
    float bias[4];
    const float* wp = w  + ((size_t)i * SS + j0) * NUNITS;
    const float* bp = bb + ((size_t)i * SS + j0) * NUNITS;

#pragma unroll
    for (int jj = 0; jj < 4; jj++) {
        float bs = 0.0f;
#pragma unroll
        for (int t = 0; t < 9; t++) {
            float ww = __ldg(wp + jj * 9 + t);
            // valid_i mask: (i + t/3) < 512 ; t/3 is a compile-time constant here
            if (i + (t / 3) >= SS) ww = 0.0f;
            wv[jj * 9 + t] = 9.0f * ww;   // fold UNITS* into weights
            bs += __ldg(bp + jj * 9 + t);
        }
        bias[jj] = bs;
    }

    size_t out_base = (size_t)i * SS + (size_t)j0;

    for (int b = b0; b < b1; ++b) {
        const float4* dp = (const float4*)(g_diag + b * DSTRIDE + j0);
        float4 a0 = dp[0];
        float4 a1 = dp[1];
        float4 a2 = dp[2];
        float d[12] = {a0.x, a0.y, a0.z, a0.w,
                       a1.x, a1.y, a1.z, a1.w,
                       a2.x, a2.y, a2.z, a2.w};

        float s0 = bias[0], s1 = bias[1], s2 = bias[2], s3 = bias[3];
#pragma unroll
        for (int t = 0; t < 9; t++) {
            s0 = fmaf(d[t],     wv[t],      s0);
            s1 = fmaf(d[t + 1], wv[9 + t],  s1);
            s2 = fmaf(d[t + 2], wv[18 + t], s2);
            s3 = fmaf(d[t + 3], wv[27 + t], s3);
        }
        float4 o;
        o.x = s0; o.y = s1; o.z = s2; o.w = s3;
        *(float4*)(out + (size_t)b * (SS * SS) + out_base) = o;
    }
}

extern "C" void kernel_launch(void* const* d_in, const int* in_sizes, int n_in,
                              void* d_out, int out_size) {
    const float* in = (const float*)d_in[0];   // inputs (B,512,512,1) f32
    const float* w  = (const float*)d_in[1];   // w (512*512*9,) f32
    const float* bb = (const float*)d_in[2];   // b (512*512*9,) f32
    float* out = (float*)d_out;                // (B, 512*512) f32

    int B = in_sizes[0] / (SS * SS);
    if (B > MAXB) B = MAXB;

    {
        int total = B * DSTRIDE;
        int threads = 256;
        diag_kernel<<<(total + threads - 1) / threads, threads>>>(in, B);
    }

    const int NSLICE = 2;
    int bper = (B + NSLICE - 1) / NSLICE;
    dim3 grid(SS, NSLICE);
    cnn_kernel<<<grid, 128>>>(w, bb, out, B, bper);
}

// round 2
// speedup vs baseline: 1.0071x; 1.0071x over previous
#include <cuda_runtime.h>

#define SS 512
#define NUNITS 9
#define DSTRIDE 520   // 512 + 8 zero pad, float4-aligned rows
#define MAXB 128      // g_diag rows; B=100 so row b+1 always valid

__device__ float g_diag[MAXB * DSTRIDE];
__device__ float g_bias[SS * SS];

// Kernel A: gather diagonal of each batch slice; zero the pad.
__global__ void diag_kernel(const float* __restrict__ in, int B) {
    int idx = blockIdx.x * blockDim.x + threadIdx.x;
    int total = B * DSTRIDE;
    if (idx >= total) return;
    int b = idx / DSTRIDE;
    int j = idx - b * DSTRIDE;
    float v = 0.0f;
    if (j < SS) v = in[(size_t)b * SS * SS + (size_t)j * (SS + 1)];
    g_diag[idx] = v;
}

// Kernel B: bias_sum[ij] = sum_t b[ij*9 + t]; thread handles 4 ij via float4.
__global__ void bias_kernel(const float* __restrict__ bb) {
    int t4 = blockIdx.x * blockDim.x + threadIdx.x;   // 0 .. 65535
    if (t4 >= (SS * SS) / 4) return;
    const float4* bp = (const float4*)(bb + (size_t)t4 * 36);
    float v[36];
#pragma unroll
    for (int k = 0; k < 9; k++) {
        float4 q = bp[k];
        v[k * 4 + 0] = q.x; v[k * 4 + 1] = q.y; v[k * 4 + 2] = q.z; v[k * 4 + 3] = q.w;
    }
    float4 s;
    float* sp = (float*)&s;
#pragma unroll
    for (int jj = 0; jj < 4; jj++) {
        float acc = 0.0f;
#pragma unroll
        for (int t = 0; t < 9; t++) acc += v[jj * 9 + t];
        sp[jj] = acc;
    }
    *(float4*)(g_bias + (size_t)t4 * 4) = s;
}

// Kernel C: thread owns (i, j0..j0+3) and a batch slice. Weights (masked,
// pre-scaled by 9) + summed bias in registers; diag loads software-pipelined.
__global__ __launch_bounds__(128)
void cnn_kernel(const float* __restrict__ w,
                float* __restrict__ out,
                int B, int bper) {
    int i  = blockIdx.x;          // 0..511
    int j0 = threadIdx.x << 2;    // 0,4,...,508
    int b0 = blockIdx.y * bper;
    int b1 = b0 + bper;
    if (b1 > B) b1 = B;
    if (b0 >= b1) return;

    // ---- prologue: 9x LDG.128 weights + 1x LDG.128 bias sums ----
    float wv[36];
    const float4* wp4 = (const float4*)(w + ((size_t)i * SS + j0) * NUNITS);
#pragma unroll
    for (int k = 0; k < 9; k++) {
        float4 q = wp4[k];
        wv[k * 4 + 0] = q.x; wv[k * 4 + 1] = q.y;
        wv[k * 4 + 2] = q.z; wv[k * 4 + 3] = q.w;
    }
#pragma unroll
    for (int n = 0; n < 36; n++) {
        int t = n % 9;
        // valid_i: (i + t/3) < 512 ; t/3 is compile-time per n
        float m = (i + (t / 3) < SS) ? 9.0f : 0.0f;
        wv[n] *= m;
    }
    float4 bias4 = *(const float4*)(g_bias + (size_t)i * SS + j0);

    size_t out_base = (size_t)i * SS + (size_t)j0;

    // ---- pipelined batch loop ----
    const float4* dp = (const float4*)(g_diag + (size_t)b0 * DSTRIDE + j0);
    float4 c0 = dp[0], c1 = dp[1], c2 = dp[2];

    for (int b = b0; b < b1; ++b) {
        // prefetch next batch (row b+1 always in-bounds of g_diag)
        const float4* np = (const float4*)(g_diag + (size_t)(b + 1) * DSTRIDE + j0);
        float4 n0 = np[0], n1 = np[1], n2 = np[2];

        float d[12] = {c0.x, c0.y, c0.z, c0.w,
                       c1.x, c1.y, c1.z, c1.w,
                       c2.x, c2.y, c2.z, c2.w};
        float s0 = bias4.x, s1 = bias4.y, s2 = bias4.z, s3 = bias4.w;
#pragma unroll
        for (int t = 0; t < 9; t++) {
            s0 = fmaf(d[t],     wv[t],      s0);
            s1 = fmaf(d[t + 1], wv[9 + t],  s1);
            s2 = fmaf(d[t + 2], wv[18 + t], s2);
            s3 = fmaf(d[t + 3], wv[27 + t], s3);
        }
        float4 o; o.x = s0; o.y = s1; o.z = s2; o.w = s3;
        *(float4*)(out + (size_t)b * (SS * SS) + out_base) = o;

        c0 = n0; c1 = n1; c2 = n2;
    }
}

extern "C" void kernel_launch(void* const* d_in, const int* in_sizes, int n_in,
                              void* d_out, int out_size) {
    const float* in = (const float*)d_in[0];   // inputs (B,512,512,1) f32
    const float* w  = (const float*)d_in[1];   // w (512*512*9,) f32
    const float* bb = (const float*)d_in[2];   // b (512*512*9,) f32
    float* out = (float*)d_out;                // (B, 512*512) f32

    int B = in_sizes[0] / (SS * SS);
    if (B > MAXB) B = MAXB;

    {
        int total = B * DSTRIDE;
        diag_kernel<<<(total + 255) / 256, 256>>>(in, B);
    }
    {
        int t4 = (SS * SS) / 4;
        bias_kernel<<<(t4 + 255) / 256, 256>>>(bb);
    }

    const int NSLICE = 5;
    int bper = (B + NSLICE - 1) / NSLICE;
    dim3 grid(SS, NSLICE);
    cnn_kernel<<<grid, 128>>>(w, out, B, bper);
}

// round 3
// speedup vs baseline: 1.1630x; 1.1549x over previous
#include <cuda_runtime.h>

#define SS 512
#define NUNITS 9
#define DSTRIDE 520   // 512 + 8 zero pad, float4-aligned rows
#define MAXB 128      // g_diag rows; B=100 so row b+1 always valid

__device__ float g_diag[MAXB * DSTRIDE];
__device__ float g_bias[SS * SS];

// Fused prep kernel: low blocks do the bias reduction (streaming 9.4 MB),
// high blocks do the diagonal gather (latency/row-activation bound) — the two
// overlap instead of running serially.
__global__ void prep_kernel(const float* __restrict__ in,
                            const float* __restrict__ bb,
                            int B, int nbias_blocks) {
    if (blockIdx.x < (unsigned)nbias_blocks) {
        // bias: g_bias[ij] = sum_t bb[ij*9+t]; one float4 of ij per thread
        int t4 = blockIdx.x * blockDim.x + threadIdx.x;
        if (t4 >= (SS * SS) / 4) return;
        const float4* bp = (const float4*)(bb + (size_t)t4 * 36);
        float v[36];
#pragma unroll
        for (int k = 0; k < 9; k++) {
            float4 q = bp[k];
            v[k * 4 + 0] = q.x; v[k * 4 + 1] = q.y;
            v[k * 4 + 2] = q.z; v[k * 4 + 3] = q.w;
        }
        float4 s;
        float* sp = (float*)&s;
#pragma unroll
        for (int jj = 0; jj < 4; jj++) {
            float acc = 0.0f;
#pragma unroll
            for (int t = 0; t < 9; t++) acc += v[jj * 9 + t];
            sp[jj] = acc;
        }
        *(float4*)(g_bias + (size_t)t4 * 4) = s;
    } else {
        // diag gather + zero pad
        int idx = (blockIdx.x - nbias_blocks) * blockDim.x + threadIdx.x;
        int total = B * DSTRIDE;
        if (idx >= total) return;
        int b = idx / DSTRIDE;
        int j = idx - b * DSTRIDE;
        float v = 0.0f;
        if (j < SS) v = in[(size_t)b * SS * SS + (size_t)j * (SS + 1)];
        g_diag[idx] = v;
    }
}

// Main kernel. (128, 6) launch bounds -> ~85 regs available: the 36 weight
// registers + 12-float diag window + prefetch window all stay in RF (the R1/R2
// version was silently spilling at the 64-reg default cap).
__global__ __launch_bounds__(128, 6)
void cnn_kernel(const float* __restrict__ w,
                float* __restrict__ out,
                int B, int bper) {
    int i  = blockIdx.x;          // 0..511
    int j0 = threadIdx.x << 2;    // 0,4,...,508
    int b0 = blockIdx.y * bper;
    int b1 = b0 + bper;
    if (b1 > B) b1 = B;
    if (b0 >= b1) return;

    // ---- prologue: 9x LDG.128 weights + 1x LDG.128 bias sums ----
    float wv[36];
    const float4* wp4 = (const float4*)(w + ((size_t)i * SS + j0) * NUNITS);
#pragma unroll
    for (int k = 0; k < 9; k++) {
        float4 q = wp4[k];
        wv[k * 4 + 0] = q.x; wv[k * 4 + 1] = q.y;
        wv[k * 4 + 2] = q.z; wv[k * 4 + 3] = q.w;
    }
#pragma unroll
    for (int n = 0; n < 36; n++) {
        int t = n % 9;
        // valid_i: (i + t/3) < 512 ; t/3 is compile-time per n
        float m = (i + (t / 3) < SS) ? 9.0f : 0.0f;
        wv[n] *= m;
    }
    float4 bias4 = *(const float4*)(g_bias + (size_t)i * SS + j0);

    // ---- pipelined batch loop ----
    const float4* dq = (const float4*)(g_diag + (size_t)b0 * DSTRIDE + j0);
    float* op = out + (size_t)b0 * (SS * SS) + (size_t)i * SS + j0;
    float4 c0 = dq[0], c1 = dq[1], c2 = dq[2];

    for (int b = b0; b < b1; ++b) {
        dq += DSTRIDE / 4;                 // next batch row (always in-bounds)
        float4 n0 = dq[0], n1 = dq[1], n2 = dq[2];

        float d[12] = {c0.x, c0.y, c0.z, c0.w,
                       c1.x, c1.y, c1.z, c1.w,
                       c2.x, c2.y, c2.z, c2.w};
        float s0 = bias4.x, s1 = bias4.y, s2 = bias4.z, s3 = bias4.w;
#pragma unroll
        for (int t = 0; t < 9; t++) {
            s0 = fmaf(d[t],     wv[t],      s0);
            s1 = fmaf(d[t + 1], wv[9 + t],  s1);
            s2 = fmaf(d[t + 2], wv[18 + t], s2);
            s3 = fmaf(d[t + 3], wv[27 + t], s3);
        }
        float4 o; o.x = s0; o.y = s1; o.z = s2; o.w = s3;
        *(float4*)op = o;
        op += SS * SS;

        c0 = n0; c1 = n1; c2 = n2;
    }
}

extern "C" void kernel_launch(void* const* d_in, const int* in_sizes, int n_in,
                              void* d_out, int out_size) {
    const float* in = (const float*)d_in[0];   // inputs (B,512,512,1) f32
    const float* w  = (const float*)d_in[1];   // w (512*512*9,) f32
    const float* bb = (const float*)d_in[2];   // b (512*512*9,) f32
    float* out = (float*)d_out;                // (B, 512*512) f32

    int B = in_sizes[0] / (SS * SS);
    if (B > MAXB) B = MAXB;

    {
        int nbias_blocks = ((SS * SS) / 4 + 255) / 256;          // 256
        int ndiag_blocks = (B * DSTRIDE + 255) / 256;            // ~204
        prep_kernel<<<nbias_blocks + ndiag_blocks, 256>>>(in, bb, B, nbias_blocks);
    }

    const int NSLICE = 5;
    int bper = (B + NSLICE - 1) / NSLICE;
    dim3 grid(SS, NSLICE);
    cnn_kernel<<<grid, 128>>>(w, out, B, bper);
}